// round 2
// baseline (speedup 1.0000x reference)
#include <cuda_runtime.h>

// ---------------- problem constants (max sizes for static scratch) ----------
#define NMAX 50000
#define EMAX 600000
#define GMAX 256
#define DH 128

// ---------------- device scratch ----------------
__device__ float g_agg[(size_t)NMAX * DH];
__device__ float g_hA [(size_t)NMAX * DH];
__device__ float g_hB [(size_t)NMAX * DH];
__device__ int   g_deg[NMAX];
__device__ int   g_rowptr[NMAX + 1];
__device__ int   g_cursor[NMAX];
__device__ int   g_srcs[EMAX];
__device__ float g_gcnt[GMAX];

// ---------------- CSR build ----------------
__global__ void zero_deg_kernel(int n) {
    int i = blockIdx.x * blockDim.x + threadIdx.x;
    if (i < n) g_deg[i] = 0;
}

__global__ void count_deg_kernel(const int* __restrict__ dst, int E, int n) {
    int e = blockIdx.x * blockDim.x + threadIdx.x;
    if (e < E) {
        int d = dst[e];
        if (d >= 0 && d < n) atomicAdd(&g_deg[d], 1);
    }
}

// single-block exclusive scan over deg -> rowptr (+ copy to cursor)
__global__ void scan_kernel(int n) {
    __shared__ int sh[1024];
    int tid = threadIdx.x;
    int chunk = (n + 1023) / 1024;
    int beg = tid * chunk;
    int end = min(beg + chunk, n);
    int s = 0;
    for (int i = beg; i < end; i++) s += g_deg[i];
    sh[tid] = s;
    __syncthreads();
    for (int off = 1; off < 1024; off <<= 1) {
        int v = (tid >= off) ? sh[tid - off] : 0;
        __syncthreads();
        sh[tid] += v;
        __syncthreads();
    }
    int run = sh[tid] - s;   // exclusive prefix for this chunk
    for (int i = beg; i < end; i++) {
        g_rowptr[i] = run;
        g_cursor[i] = run;
        run += g_deg[i];
    }
    if (tid == 1023) g_rowptr[n] = sh[1023];
}

__global__ void scatter_kernel(const int* __restrict__ src,
                               const int* __restrict__ dst, int E, int n) {
    int e = blockIdx.x * blockDim.x + threadIdx.x;
    if (e < E) {
        int d = dst[e];
        int s = src[e];
        if (d >= 0 && d < n && s >= 0 && s < n) {
            int p = atomicAdd(&g_cursor[d], 1);
            if (p < EMAX) g_srcs[p] = s;
        }
    }
}

// ---------------- mean aggregation: one warp per node ----------------
template <int D>
__global__ void agg_kernel(const float* __restrict__ x, float* __restrict__ agg, int n) {
    int gw   = (blockIdx.x * blockDim.x + threadIdx.x) >> 5;
    int lane = threadIdx.x & 31;
    if (gw >= n) return;
    int beg = g_rowptr[gw];
    int end = g_rowptr[gw + 1];
    constexpr int C = D / 32;
    float acc[C];
#pragma unroll
    for (int c = 0; c < C; c++) acc[c] = 0.0f;

    for (int j = beg; j < end; j++) {
        int s = g_srcs[j];
        const float* row = x + (size_t)s * D;
#pragma unroll
        for (int c = 0; c < C; c++) acc[c] += __ldg(row + lane + 32 * c);
    }
    float inv = 1.0f / fmaxf((float)(end - beg), 1.0f);
#pragma unroll
    for (int c = 0; c < C; c++) agg[(size_t)gw * D + lane + 32 * c] = acc[c] * inv;
}

// ---------------- fused SAGE GEMM: out = agg@Wl + x@Wr + b (+relu) ---------
// Tile: M=128 rows, N=128 cols, 256 threads, 4x16 outputs per thread.
// A is the virtual concat [agg | x] of width 2K; weights Wcat=[Wl;Wr] in smem.
template <int K, bool RELU>
__global__ __launch_bounds__(256)
void gemm_fused(const float* __restrict__ A1, const float* __restrict__ A2,
                const float* __restrict__ Wl, const float* __restrict__ Wr,
                const float* __restrict__ bias, float* __restrict__ out, int n) {
    extern __shared__ float smem[];
    float* Ws = smem;                     // [2K][128]
    float* As = smem + 2 * K * 128;       // [8][128]  (transposed chunk: As[kk][row])

    const int tid  = threadIdx.x;
    const int colg = tid & 7;             // 0..7  -> cols colg*4 + j*32 + q
    const int rowg = tid >> 3;            // 0..31 -> rows rowg*4 + r
    const int m0   = blockIdx.x * 128;

    // load concatenated weights into smem (float4)
    for (int idx = tid * 4; idx < 2 * K * 128; idx += 256 * 4) {
        int r = idx >> 7;
        int c = idx & 127;
        const float* w = (r < K) ? (Wl + (size_t)r * 128 + c)
                                 : (Wr + (size_t)(r - K) * 128 + c);
        *(float4*)(Ws + idx) = *(const float4*)w;
    }

    float acc[4][16];
#pragma unroll
    for (int r = 0; r < 4; r++)
#pragma unroll
        for (int c = 0; c < 16; c++) acc[r][c] = 0.0f;

    const int lrow = tid >> 1;      // 0..127: row loaded by this thread
    const int lhal = tid & 1;       // which half of the 8-wide k chunk

    for (int k0 = 0; k0 < 2 * K; k0 += 8) {
        const float* Asrc;
        int kb;
        if (k0 < K) { Asrc = A1; kb = k0; }
        else        { Asrc = A2; kb = k0 - K; }

        int grow = m0 + lrow;
        if (grow > n - 1) grow = n - 1;
        float4 v = *(const float4*)(Asrc + (size_t)grow * K + kb + lhal * 4);
        __syncthreads();              // protect previous iteration's As reads
        As[(lhal * 4 + 0) * 128 + lrow] = v.x;
        As[(lhal * 4 + 1) * 128 + lrow] = v.y;
        As[(lhal * 4 + 2) * 128 + lrow] = v.z;
        As[(lhal * 4 + 3) * 128 + lrow] = v.w;
        __syncthreads();

#pragma unroll
        for (int kk = 0; kk < 8; kk++) {
            float4 a = *(float4*)(As + kk * 128 + rowg * 4);
            float av[4] = {a.x, a.y, a.z, a.w};
#pragma unroll
            for (int j = 0; j < 4; j++) {
                float4 b = *(float4*)(Ws + (k0 + kk) * 128 + colg * 4 + j * 32);
#pragma unroll
                for (int r = 0; r < 4; r++) {
                    acc[r][j * 4 + 0] += av[r] * b.x;
                    acc[r][j * 4 + 1] += av[r] * b.y;
                    acc[r][j * 4 + 2] += av[r] * b.z;
                    acc[r][j * 4 + 3] += av[r] * b.w;
                }
            }
        }
    }

    // epilogue
#pragma unroll
    for (int r = 0; r < 4; r++) {
        int grow = m0 + rowg * 4 + r;
        if (grow < n) {
#pragma unroll
            for (int j = 0; j < 4; j++) {
                float4 bv = *(const float4*)(bias + colg * 4 + j * 32);
                float4 o;
                o.x = acc[r][j * 4 + 0] + bv.x;
                o.y = acc[r][j * 4 + 1] + bv.y;
                o.z = acc[r][j * 4 + 2] + bv.z;
                o.w = acc[r][j * 4 + 3] + bv.w;
                if (RELU) {
                    o.x = fmaxf(o.x, 0.0f); o.y = fmaxf(o.y, 0.0f);
                    o.z = fmaxf(o.z, 0.0f); o.w = fmaxf(o.w, 0.0f);
                }
                *(float4*)(out + (size_t)grow * 128 + colg * 4 + j * 32) = o;
            }
        }
    }
}

// ---------------- global mean pool ----------------
__global__ void pool_zero_kernel(float* out, int G) {
    int i = blockIdx.x * blockDim.x + threadIdx.x;
    if (i < G * 128) out[i] = 0.0f;
    if (i < G) g_gcnt[i] = 0.0f;
}

__global__ void pool_acc_kernel(const float* __restrict__ h,
                                const int* __restrict__ batch,
                                float* __restrict__ out, int n, int G) {
    const int NPW = 16;
    int gw   = (blockIdx.x * blockDim.x + threadIdx.x) >> 5;
    int lane = threadIdx.x & 31;
    int beg = gw * NPW;
    if (beg >= n) return;
    int end = min(beg + NPW, n);
    float a0 = 0, a1 = 0, a2 = 0, a3 = 0;
    int cur = min(max(batch[beg], 0), G - 1);
    int cnt = 0;
    for (int i = beg; i < end; i++) {
        int b = min(max(batch[i], 0), G - 1);
        if (b != cur) {
            atomicAdd(&out[cur * 128 + lane +  0], a0);
            atomicAdd(&out[cur * 128 + lane + 32], a1);
            atomicAdd(&out[cur * 128 + lane + 64], a2);
            atomicAdd(&out[cur * 128 + lane + 96], a3);
            if (lane == 0) atomicAdd(&g_gcnt[cur], (float)cnt);
            a0 = a1 = a2 = a3 = 0.0f;
            cnt = 0;
            cur = b;
        }
        const float* row = h + (size_t)i * 128;
        a0 += row[lane];  a1 += row[lane + 32];
        a2 += row[lane + 64]; a3 += row[lane + 96];
        cnt++;
    }
    atomicAdd(&out[cur * 128 + lane +  0], a0);
    atomicAdd(&out[cur * 128 + lane + 32], a1);
    atomicAdd(&out[cur * 128 + lane + 64], a2);
    atomicAdd(&out[cur * 128 + lane + 96], a3);
    if (lane == 0) atomicAdd(&g_gcnt[cur], (float)cnt);
}

__global__ void pool_div_kernel(float* out, int G) {
    int i = blockIdx.x * blockDim.x + threadIdx.x;
    if (i < G * 128) out[i] /= fmaxf(g_gcnt[i >> 7], 1.0f);
}

// ---------------- launch ----------------
extern "C" void kernel_launch(void* const* d_in, const int* in_sizes, int n_in,
                              void* d_out, int out_size) {
    const float* x     = (const float*)d_in[0];
    const int*   ei    = (const int*)d_in[1];     // int32 (JAX downcasts int64)
    const int*   batch = (const int*)d_in[2];     // int32
    const float* Wl1 = (const float*)d_in[3];
    const float* bl1 = (const float*)d_in[4];
    const float* Wr1 = (const float*)d_in[5];
    const float* Wl2 = (const float*)d_in[6];
    const float* bl2 = (const float*)d_in[7];
    const float* Wr2 = (const float*)d_in[8];
    const float* Wl3 = (const float*)d_in[9];
    const float* bl3 = (const float*)d_in[10];
    const float* Wr3 = (const float*)d_in[11];
    float* out = (float*)d_out;

    const int n = in_sizes[0] / 64;       // 50000
    const int E = in_sizes[1] / 2;        // 600000
    const int G = out_size / 128;         // 64

    const int* src = ei;
    const int* dst = ei + E;

    // scratch pointers via symbols
    void *p_agg, *p_hA, *p_hB;
    cudaGetSymbolAddress(&p_agg, g_agg);
    cudaGetSymbolAddress(&p_hA, g_hA);
    cudaGetSymbolAddress(&p_hB, g_hB);
    float* agg = (float*)p_agg;
    float* hA  = (float*)p_hA;
    float* hB  = (float*)p_hB;

    const int smem1 = (2 * 64 * 128 + 8 * 128) * 4;    // 69632
    const int smem2 = (2 * 128 * 128 + 8 * 128) * 4;   // 135168
    cudaFuncSetAttribute(gemm_fused<64,  true >, cudaFuncAttributeMaxDynamicSharedMemorySize, smem1);
    cudaFuncSetAttribute(gemm_fused<128, true >, cudaFuncAttributeMaxDynamicSharedMemorySize, smem2);
    cudaFuncSetAttribute(gemm_fused<128, false>, cudaFuncAttributeMaxDynamicSharedMemorySize, smem2);

    // ---- CSR build ----
    zero_deg_kernel<<<(n + 255) / 256, 256>>>(n);
    count_deg_kernel<<<(E + 255) / 256, 256>>>(dst, E, n);
    scan_kernel<<<1, 1024>>>(n);
    scatter_kernel<<<(E + 255) / 256, 256>>>(src, dst, E, n);

    const int aggBlocks = (n * 32 + 255) / 256;
    const int gemmBlocks = (n + 127) / 128;

    // ---- layer 1 ----
    agg_kernel<64><<<aggBlocks, 256>>>(x, agg, n);
    gemm_fused<64, true><<<gemmBlocks, 256, smem1>>>(agg, x, Wl1, Wr1, bl1, hA, n);

    // ---- layer 2 ----
    agg_kernel<128><<<aggBlocks, 256>>>(hA, agg, n);
    gemm_fused<128, true><<<gemmBlocks, 256, smem2>>>(agg, hA, Wl2, Wr2, bl2, hB, n);

    // ---- layer 3 ----
    agg_kernel<128><<<aggBlocks, 256>>>(hB, agg, n);
    gemm_fused<128, false><<<gemmBlocks, 256, smem2>>>(agg, hB, Wl3, Wr3, bl3, hA, n);

    // ---- global mean pool ----
    pool_zero_kernel<<<(G * 128 + 255) / 256, 256>>>(out, G);
    int poolWarps = (n + 15) / 16;
    pool_acc_kernel<<<(poolWarps * 32 + 255) / 256, 256>>>(hA, batch, out, n, G);
    pool_div_kernel<<<(G * 128 + 255) / 256, 256>>>(out, G);
}

// round 4
// speedup vs baseline: 1.5002x; 1.5002x over previous
#include <cuda_runtime.h>
#include <cuda_bf16.h>
#include <cstdint>

// ---------------- problem constants ----------------
#define NMAX 50000
#define EMAX 600000
#define GMAX 256
#define DH 128

// ---------------- device scratch ----------------
__device__ float g_agg[(size_t)NMAX * DH];
__device__ float g_hA [(size_t)NMAX * DH];
__device__ float g_hB [(size_t)NMAX * DH];
__device__ int   g_deg[NMAX];
__device__ int   g_rowptr[NMAX + 1];
__device__ int   g_cursor[NMAX];
__device__ int   g_srcs[EMAX];
__device__ float g_gcnt[GMAX];
// pre-split bf16 hi/lo weight images, padded [n][2K+8] layout
// L1: 128*264 = 33792, L2/L3: 128*520 = 66560 each
__device__ unsigned short g_Bimg[167168];

// ---------------- CSR build ----------------
__global__ void zero_deg_kernel(int n) {
    int i = blockIdx.x * blockDim.x + threadIdx.x;
    if (i < n) g_deg[i] = 0;
}

__global__ void count_deg_kernel(const int* __restrict__ dst, int E, int n) {
    int e = blockIdx.x * blockDim.x + threadIdx.x;
    if (e < E) {
        int d = dst[e];
        if (d >= 0 && d < n) atomicAdd(&g_deg[d], 1);
    }
}

__global__ void scan_kernel(int n) {
    __shared__ int sh[1024];
    int tid = threadIdx.x;
    int chunk = (n + 1023) / 1024;
    int beg = tid * chunk;
    int end = min(beg + chunk, n);
    int s = 0;
    for (int i = beg; i < end; i++) s += g_deg[i];
    sh[tid] = s;
    __syncthreads();
    for (int off = 1; off < 1024; off <<= 1) {
        int v = (tid >= off) ? sh[tid - off] : 0;
        __syncthreads();
        sh[tid] += v;
        __syncthreads();
    }
    int run = sh[tid] - s;
    for (int i = beg; i < end; i++) {
        g_rowptr[i] = run;
        g_cursor[i] = run;
        run += g_deg[i];
    }
    if (tid == 1023) g_rowptr[n] = sh[1023];
}

__global__ void scatter_kernel(const int* __restrict__ src,
                               const int* __restrict__ dst, int E, int n) {
    int e = blockIdx.x * blockDim.x + threadIdx.x;
    if (e < E) {
        int d = dst[e];
        int s = src[e];
        if (d >= 0 && d < n && s >= 0 && s < n) {
            int p = atomicAdd(&g_cursor[d], 1);
            if (p < EMAX) g_srcs[p] = s;
        }
    }
}

// ---------------- mean aggregation: one warp per node ----------------
template <int D>
__global__ void agg_kernel(const float* __restrict__ x, float* __restrict__ agg, int n) {
    int gw   = (blockIdx.x * blockDim.x + threadIdx.x) >> 5;
    int lane = threadIdx.x & 31;
    if (gw >= n) return;
    int beg = g_rowptr[gw];
    int end = g_rowptr[gw + 1];
    constexpr int C = D / 32;
    float acc[C];
#pragma unroll
    for (int c = 0; c < C; c++) acc[c] = 0.0f;
    for (int j = beg; j < end; j++) {
        int s = g_srcs[j];
        const float* row = x + (size_t)s * D;
#pragma unroll
        for (int c = 0; c < C; c++) acc[c] += __ldg(row + lane + 32 * c);
    }
    float inv = 1.0f / fmaxf((float)(end - beg), 1.0f);
#pragma unroll
    for (int c = 0; c < C; c++) agg[(size_t)gw * D + lane + 32 * c] = acc[c] * inv;
}

// ---------------- weight image prep ----------------
// B image: bf16 [n=128][stride = 2*Ktot + 8], hi at k in [0,Ktot), lo at [Ktot,2Ktot).
// Wcat = [Wl; Wr] along K (row-major [K][128]); B[n][k] = Wcat[k][n].
__global__ void prep_B_kernel(const float* __restrict__ Wl, const float* __restrict__ Wr,
                              unsigned short* __restrict__ img, int chunks) {
    int strideB = chunks * 128 + 8;
    int Ktot    = chunks * 64;
    int total   = 128 * strideB;
    int t = blockIdx.x * blockDim.x + threadIdx.x;
    if (t >= total) return;
    int nn = t / strideB;
    int kk = t - nn * strideB;
    if (kk < Ktot) {
        int half = chunks * 32;     // fp32 rows per source matrix
        const float* W; int k;
        if (kk < half) { W = Wl; k = kk; } else { W = Wr; k = kk - half; }
        float v = W[(size_t)k * 128 + nn];
        __nv_bfloat16 h = __float2bfloat16_rn(v);
        __nv_bfloat16 l = __float2bfloat16_rn(v - __bfloat162float(h));
        img[nn * strideB + kk]        = __bfloat16_as_ushort(h);
        img[nn * strideB + Ktot + kk] = __bfloat16_as_ushort(l);
    } else if (kk >= 2 * Ktot) {
        img[t] = 0;
    }
}

// ---------------- mma.sync helper ----------------
__device__ __forceinline__ void mma16816(float* c, const uint32_t* a,
                                         uint32_t b0, uint32_t b1) {
    asm volatile(
        "mma.sync.aligned.m16n8k16.row.col.f32.bf16.bf16.f32 "
        "{%0,%1,%2,%3}, {%4,%5,%6,%7}, {%8,%9}, {%0,%1,%2,%3};"
        : "+f"(c[0]), "+f"(c[1]), "+f"(c[2]), "+f"(c[3])
        : "r"(a[0]), "r"(a[1]), "r"(a[2]), "r"(a[3]), "r"(b0), "r"(b1));
}

// ---------------- tensor-core fused SAGE GEMM ----------------
// out[m,0:128] = [agg | x] @ [Wl;Wr] + b (+relu), fp32 via 3-term bf16 split:
//   C = Ah*Bh + Al*Bh + Ah*Bl   (fp32 accumulate in registers)
// CTA: 128-row M tile x 128 N, 256 threads, 8 warps (4 m x 2 n), warp tile 32x64.
template <int CHUNKS, bool RELU>
__global__ __launch_bounds__(256)
void sage_mma(const float* __restrict__ A1, const float* __restrict__ A2,
              const unsigned short* __restrict__ Bimg, const float* __restrict__ bias,
              float* __restrict__ out, int n) {
    constexpr int STRIDEB = CHUNKS * 128 + 8;   // bf16 units per B row
    constexpr int KTOT    = CHUNKS * 64;        // hi-part K length
    constexpr int ASTRIDE = 136;                // bf16 units per A row (64 hi + 64 lo + 8 pad)
    constexpr int ASTR32  = CHUNKS * 32;        // fp32 row stride of A1/A2

    extern __shared__ unsigned short sm[];
    unsigned short* As = sm;                    // 128 * 136
    unsigned short* Bs = sm + 128 * ASTRIDE;    // 128 * STRIDEB

    const int tid  = threadIdx.x;
    const int wid  = tid >> 5;
    const int lane = tid & 31;
    const int tq   = lane >> 2;      // 0..7
    const int tr   = lane & 3;       // 0..3
    const int wm   = wid & 3;        // 4 warps along M (32 rows each)
    const int wn   = wid >> 2;       // 2 warps along N (64 cols each)
    const int m0   = blockIdx.x * 128;

    // copy weight image into smem verbatim (16B vectors)
    {
        const float4* bsrc = (const float4*)Bimg;
        float4* bdst = (float4*)Bs;
        constexpr int NV = 128 * STRIDEB * 2 / 16;
        for (int i = tid; i < NV; i += 256) bdst[i] = bsrc[i];
    }

    float acc[2][8][4];
#pragma unroll
    for (int a = 0; a < 2; a++)
#pragma unroll
        for (int b = 0; b < 8; b++)
#pragma unroll
            for (int q = 0; q < 4; q++) acc[a][b][q] = 0.0f;

    for (int c = 0; c < CHUNKS; ++c) {
        __syncthreads();   // B copy done (c==0) / previous-chunk A reads done

        // convert A chunk c: 128 rows x 64 fp32 -> hi/lo bf16 pairs in smem
        const float* src = (c < CHUNKS / 2) ? A1 : A2;
        int kb = (c & (CHUNKS / 2 - 1)) * 64;
#pragma unroll
        for (int i = 0; i < 16; i++) {
            int p   = i * 256 + tid;
            int row = p >> 5;
            int k2  = p & 31;
            int grow = min(m0 + row, n - 1);
            float2 v = *(const float2*)(src + (size_t)grow * ASTR32 + kb + 2 * k2);
            __nv_bfloat16 h0 = __float2bfloat16_rn(v.x);
            __nv_bfloat16 h1 = __float2bfloat16_rn(v.y);
            __nv_bfloat16 l0 = __float2bfloat16_rn(v.x - __bfloat162float(h0));
            __nv_bfloat16 l1 = __float2bfloat16_rn(v.y - __bfloat162float(h1));
            uint32_t hp = ((uint32_t)__bfloat16_as_ushort(h1) << 16) | __bfloat16_as_ushort(h0);
            uint32_t lp = ((uint32_t)__bfloat16_as_ushort(l1) << 16) | __bfloat16_as_ushort(l0);
            *(uint32_t*)(As + row * ASTRIDE + 2 * k2)      = hp;
            *(uint32_t*)(As + row * ASTRIDE + 64 + 2 * k2) = lp;
        }
        __syncthreads();

        // 3 emulation passes x 4 k16-steps
#pragma unroll
        for (int pass = 0; pass < 3; pass++) {
            const int apos  = (pass == 1) ? 64 : 0;           // Al for pass 1
            const int bbase = c * 64 + ((pass == 2) ? KTOT : 0); // Bl for pass 2
#pragma unroll
            for (int ks = 0; ks < 4; ks++) {
                uint32_t af[2][4];
#pragma unroll
                for (int ma = 0; ma < 2; ma++) {
                    const unsigned short* ap =
                        As + (wm * 32 + ma * 16 + tq) * ASTRIDE + apos + ks * 16 + 2 * tr;
                    af[ma][0] = *(const uint32_t*)(ap);
                    af[ma][1] = *(const uint32_t*)(ap + 8 * ASTRIDE);
                    af[ma][2] = *(const uint32_t*)(ap + 8);
                    af[ma][3] = *(const uint32_t*)(ap + 8 * ASTRIDE + 8);
                }
#pragma unroll
                for (int nb = 0; nb < 8; nb++) {
                    const unsigned short* bp =
                        Bs + (wn * 64 + nb * 8 + tq) * STRIDEB + bbase + ks * 16 + 2 * tr;
                    uint32_t b0 = *(const uint32_t*)(bp);
                    uint32_t b1 = *(const uint32_t*)(bp + 8);
                    mma16816(acc[0][nb], af[0], b0, b1);
                    mma16816(acc[1][nb], af[1], b0, b1);
                }
            }
        }
    }

    // epilogue: +bias, relu, float2 stores
#pragma unroll
    for (int ma = 0; ma < 2; ma++) {
        int row = m0 + wm * 32 + ma * 16 + tq;
#pragma unroll
        for (int nb = 0; nb < 8; nb++) {
            int col = wn * 64 + nb * 8 + 2 * tr;
            float2 bv = *(const float2*)(bias + col);
            if (row < n) {
                float2 o;
                o.x = acc[ma][nb][0] + bv.x;
                o.y = acc[ma][nb][1] + bv.y;
                if (RELU) { o.x = fmaxf(o.x, 0.0f); o.y = fmaxf(o.y, 0.0f); }
                *(float2*)(out + (size_t)row * 128 + col) = o;
            }
            if (row + 8 < n) {
                float2 o;
                o.x = acc[ma][nb][2] + bv.x;
                o.y = acc[ma][nb][3] + bv.y;
                if (RELU) { o.x = fmaxf(o.x, 0.0f); o.y = fmaxf(o.y, 0.0f); }
                *(float2*)(out + (size_t)(row + 8) * 128 + col) = o;
            }
        }
    }
}

// ---------------- global mean pool ----------------
__global__ void pool_zero_kernel(float* out, int G) {
    int i = blockIdx.x * blockDim.x + threadIdx.x;
    if (i < G * 128) out[i] = 0.0f;
    if (i < G) g_gcnt[i] = 0.0f;
}

__global__ void pool_acc_kernel(const float* __restrict__ h,
                                const int* __restrict__ batch,
                                float* __restrict__ out, int n, int G) {
    const int NPW = 16;
    int gw   = (blockIdx.x * blockDim.x + threadIdx.x) >> 5;
    int lane = threadIdx.x & 31;
    int beg = gw * NPW;
    if (beg >= n) return;
    int end = min(beg + NPW, n);
    float a0 = 0, a1 = 0, a2 = 0, a3 = 0;
    int cur = min(max(batch[beg], 0), G - 1);
    int cnt = 0;
    for (int i = beg; i < end; i++) {
        int b = min(max(batch[i], 0), G - 1);
        if (b != cur) {
            atomicAdd(&out[cur * 128 + lane +  0], a0);
            atomicAdd(&out[cur * 128 + lane + 32], a1);
            atomicAdd(&out[cur * 128 + lane + 64], a2);
            atomicAdd(&out[cur * 128 + lane + 96], a3);
            if (lane == 0) atomicAdd(&g_gcnt[cur], (float)cnt);
            a0 = a1 = a2 = a3 = 0.0f;
            cnt = 0;
            cur = b;
        }
        const float* row = h + (size_t)i * 128;
        a0 += row[lane];      a1 += row[lane + 32];
        a2 += row[lane + 64]; a3 += row[lane + 96];
        cnt++;
    }
    atomicAdd(&out[cur * 128 + lane +  0], a0);
    atomicAdd(&out[cur * 128 + lane + 32], a1);
    atomicAdd(&out[cur * 128 + lane + 64], a2);
    atomicAdd(&out[cur * 128 + lane + 96], a3);
    if (lane == 0) atomicAdd(&g_gcnt[cur], (float)cnt);
}

__global__ void pool_div_kernel(float* out, int G) {
    int i = blockIdx.x * blockDim.x + threadIdx.x;
    if (i < G * 128) out[i] /= fmaxf(g_gcnt[i >> 7], 1.0f);
}

// ---------------- launch ----------------
extern "C" void kernel_launch(void* const* d_in, const int* in_sizes, int n_in,
                              void* d_out, int out_size) {
    const float* x     = (const float*)d_in[0];
    const int*   ei    = (const int*)d_in[1];
    const int*   batch = (const int*)d_in[2];
    const float* Wl1 = (const float*)d_in[3];
    const float* bl1 = (const float*)d_in[4];
    const float* Wr1 = (const float*)d_in[5];
    const float* Wl2 = (const float*)d_in[6];
    const float* bl2 = (const float*)d_in[7];
    const float* Wr2 = (const float*)d_in[8];
    const float* Wl3 = (const float*)d_in[9];
    const float* bl3 = (const float*)d_in[10];
    const float* Wr3 = (const float*)d_in[11];
    float* out = (float*)d_out;

    const int n = in_sizes[0] / 64;       // 50000
    const int E = in_sizes[1] / 2;        // 600000
    const int G = out_size / 128;         // 64

    const int* src = ei;
    const int* dst = ei + E;

    void *p_agg, *p_hA, *p_hB, *p_Bimg;
    cudaGetSymbolAddress(&p_agg, g_agg);
    cudaGetSymbolAddress(&p_hA, g_hA);
    cudaGetSymbolAddress(&p_hB, g_hB);
    cudaGetSymbolAddress(&p_Bimg, g_Bimg);
    float* agg = (float*)p_agg;
    float* hA  = (float*)p_hA;
    float* hB  = (float*)p_hB;
    unsigned short* Bimg = (unsigned short*)p_Bimg;

    const int smem1 = (128 * 136 + 128 * 264) * 2;   // 102400 (CHUNKS=2)
    const int smem2 = (128 * 136 + 128 * 520) * 2;   // 167936 (CHUNKS=4)
    cudaFuncSetAttribute(sage_mma<2, true >, cudaFuncAttributeMaxDynamicSharedMemorySize, smem1);
    cudaFuncSetAttribute(sage_mma<4, true >, cudaFuncAttributeMaxDynamicSharedMemorySize, smem2);
    cudaFuncSetAttribute(sage_mma<4, false>, cudaFuncAttributeMaxDynamicSharedMemorySize, smem2);

    // ---- weight images (padded [n][2K+8] bf16 hi/lo) ----
    prep_B_kernel<<<(128 * 264 + 255) / 256, 256>>>(Wl1, Wr1, Bimg,          2);
    prep_B_kernel<<<(128 * 520 + 255) / 256, 256>>>(Wl2, Wr2, Bimg + 33792,  4);
    prep_B_kernel<<<(128 * 520 + 255) / 256, 256>>>(Wl3, Wr3, Bimg + 100352, 4);

    // ---- CSR build ----
    zero_deg_kernel<<<(n + 255) / 256, 256>>>(n);
    count_deg_kernel<<<(E + 255) / 256, 256>>>(dst, E, n);
    scan_kernel<<<1, 1024>>>(n);
    scatter_kernel<<<(E + 255) / 256, 256>>>(src, dst, E, n);

    const int aggBlocks = (n * 32 + 255) / 256;
    const int gemmBlocks = (n + 127) / 128;

    // ---- layer 1 ----
    agg_kernel<64><<<aggBlocks, 256>>>(x, agg, n);
    sage_mma<2, true><<<gemmBlocks, 256, smem1>>>(agg, x, Bimg, bl1, hA, n);

    // ---- layer 2 ----
    agg_kernel<128><<<aggBlocks, 256>>>(hA, agg, n);
    sage_mma<4, true><<<gemmBlocks, 256, smem2>>>(agg, hA, Bimg + 33792, bl2, hB, n);

    // ---- layer 3 ----
    agg_kernel<128><<<aggBlocks, 256>>>(hB, agg, n);
    sage_mma<4, false><<<gemmBlocks, 256, smem2>>>(agg, hB, Bimg + 100352, bl3, hA, n);

    // ---- global mean pool ----
    pool_zero_kernel<<<(G * 128 + 255) / 256, 256>>>(out, G);
    int poolWarps = (n + 15) / 16;
    pool_acc_kernel<<<(poolWarps * 32 + 255) / 256, 256>>>(hA, batch, out, n, G);
    pool_div_kernel<<<(G * 128 + 255) / 256, 256>>>(out, G);
}

// round 6
// speedup vs baseline: 1.5943x; 1.0627x over previous
#include <cuda_runtime.h>
#include <cuda_bf16.h>
#include <cstdint>

// ---------------- problem constants ----------------
#define NMAX 50000
#define EMAX 600000
#define GMAX 256
#define DH 128

// ---------------- device scratch ----------------
__device__ float g_agg[(size_t)NMAX * DH];
__device__ float g_hA [(size_t)NMAX * DH];
__device__ float g_hB [(size_t)NMAX * DH];
__device__ int   g_deg[NMAX];
__device__ int   g_rowptr[NMAX + 1];
__device__ int   g_cursor[NMAX];
__device__ int   g_srcs[EMAX];
__device__ float g_gcnt[GMAX];
// pre-split bf16 hi/lo weight images, padded [n][2K+8] layout
// L1: 128*264 = 33792, L2/L3: 128*520 = 66560 each
__device__ unsigned short g_Bimg[167168];

// ---------------- CSR build ----------------
__global__ void zero_deg_kernel(int n) {
    int i = blockIdx.x * blockDim.x + threadIdx.x;
    if (i < n) g_deg[i] = 0;
}

__global__ void count_deg_kernel(const int* __restrict__ dst, int E, int n) {
    int e = blockIdx.x * blockDim.x + threadIdx.x;
    if (e < E) {
        int d = dst[e];
        if (d >= 0 && d < n) atomicAdd(&g_deg[d], 1);
    }
}

__global__ void scan_kernel(int n) {
    __shared__ int sh[1024];
    int tid = threadIdx.x;
    int chunk = (n + 1023) / 1024;
    int beg = tid * chunk;
    int end = min(beg + chunk, n);
    int s = 0;
    for (int i = beg; i < end; i++) s += g_deg[i];
    sh[tid] = s;
    __syncthreads();
    for (int off = 1; off < 1024; off <<= 1) {
        int v = (tid >= off) ? sh[tid - off] : 0;
        __syncthreads();
        sh[tid] += v;
        __syncthreads();
    }
    int run = sh[tid] - s;
    for (int i = beg; i < end; i++) {
        g_rowptr[i] = run;
        g_cursor[i] = run;
        run += g_deg[i];
    }
    if (tid == 1023) g_rowptr[n] = sh[1023];
}

__global__ void scatter_kernel(const int* __restrict__ src,
                               const int* __restrict__ dst, int E, int n) {
    int e = blockIdx.x * blockDim.x + threadIdx.x;
    if (e < E) {
        int d = dst[e];
        int s = src[e];
        if (d >= 0 && d < n && s >= 0 && s < n) {
            int p = atomicAdd(&g_cursor[d], 1);
            if (p < EMAX) g_srcs[p] = s;
        }
    }
}

// ---------------- mean aggregation: one warp per node ----------------
template <int D>
__global__ void agg_kernel(const float* __restrict__ x, float* __restrict__ agg, int n) {
    int gw   = (blockIdx.x * blockDim.x + threadIdx.x) >> 5;
    int lane = threadIdx.x & 31;
    if (gw >= n) return;
    int beg = g_rowptr[gw];
    int end = g_rowptr[gw + 1];
    constexpr int C = D / 32;
    float acc[C];
#pragma unroll
    for (int c = 0; c < C; c++) acc[c] = 0.0f;
    for (int j = beg; j < end; j++) {
        int s = g_srcs[j];
        const float* row = x + (size_t)s * D;
#pragma unroll
        for (int c = 0; c < C; c++) acc[c] += __ldg(row + lane + 32 * c);
    }
    float inv = 1.0f / fmaxf((float)(end - beg), 1.0f);
#pragma unroll
    for (int c = 0; c < C; c++) agg[(size_t)gw * D + lane + 32 * c] = acc[c] * inv;
}

// ---------------- weight image prep ----------------
// B image: bf16 [n=128][stride = 2*Ktot + 8], hi at k in [0,Ktot), lo at [Ktot,2Ktot).
// Wcat = [Wl; Wr] along K (row-major [K][128]); B[n][k] = Wcat[k][n].
__global__ void prep_B_kernel(const float* __restrict__ Wl, const float* __restrict__ Wr,
                              unsigned short* __restrict__ img, int chunks) {
    int strideB = chunks * 128 + 8;
    int Ktot    = chunks * 64;
    int total   = 128 * strideB;
    int t = blockIdx.x * blockDim.x + threadIdx.x;
    if (t >= total) return;
    int nn = t / strideB;
    int kk = t - nn * strideB;
    if (kk < Ktot) {
        int half = chunks * 32;     // fp32 rows per source matrix
        const float* W; int k;
        if (kk < half) { W = Wl; k = kk; } else { W = Wr; k = kk - half; }
        float v = W[(size_t)k * 128 + nn];
        __nv_bfloat16 h = __float2bfloat16_rn(v);
        __nv_bfloat16 l = __float2bfloat16_rn(v - __bfloat162float(h));
        img[nn * strideB + kk]        = __bfloat16_as_ushort(h);
        img[nn * strideB + Ktot + kk] = __bfloat16_as_ushort(l);
    } else if (kk >= 2 * Ktot) {
        img[t] = 0;
    }
}

// ---------------- mma / ldmatrix helpers ----------------
__device__ __forceinline__ void mma16816(float* c, const uint32_t* a,
                                         uint32_t b0, uint32_t b1) {
    asm volatile(
        "mma.sync.aligned.m16n8k16.row.col.f32.bf16.bf16.f32 "
        "{%0,%1,%2,%3}, {%4,%5,%6,%7}, {%8,%9}, {%0,%1,%2,%3};"
        : "+f"(c[0]), "+f"(c[1]), "+f"(c[2]), "+f"(c[3])
        : "r"(a[0]), "r"(a[1]), "r"(a[2]), "r"(a[3]), "r"(b0), "r"(b1));
}

__device__ __forceinline__ void ldsm_x4(uint32_t* r, uint32_t addr) {
    asm volatile(
        "ldmatrix.sync.aligned.m8n8.x4.shared.b16 {%0,%1,%2,%3}, [%4];"
        : "=r"(r[0]), "=r"(r[1]), "=r"(r[2]), "=r"(r[3]) : "r"(addr));
}

__device__ __forceinline__ uint32_t smem_u32(const void* p) {
    uint32_t a;
    asm("{ .reg .u64 t; cvta.to.shared.u64 t, %1; cvt.u32.u64 %0, t; }"
        : "=r"(a) : "l"(p));
    return a;
}

// ---------------- persistent tensor-core fused SAGE GEMM ----------------
// out[m,0:128] = [agg | x] @ [Wl;Wr] + b (+relu), fp32 via 3-term bf16 split:
//   C = Ah*Bh + Al*Bh + Ah*Bl  (fp32 register accumulators)
// Persistent: grid=148, each CTA loads the weight image once, loops M tiles.
// CTA: 128x128 tile, 256 threads, 8 warps (4 m x 2 n), warp tile 32x64.
template <int CHUNKS, bool RELU>
__global__ __launch_bounds__(256, 1)
void sage_mma(const float* __restrict__ A1, const float* __restrict__ A2,
              const unsigned short* __restrict__ Bimg, const float* __restrict__ bias,
              float* __restrict__ out, int n, int nTiles) {
    constexpr int STRIDEB = CHUNKS * 128 + 8;   // bf16 units per B row
    constexpr int KTOT    = CHUNKS * 64;        // hi-part K length (bf16 units)
    constexpr int ASTRIDE = 136;                // bf16 units per A row (64 hi + 64 lo + 8 pad)
    constexpr int ASTR32  = CHUNKS * 32;        // fp32 row stride of A1/A2

    extern __shared__ unsigned short sm[];
    unsigned short* As = sm;                    // 128 * 136
    unsigned short* Bs = sm + 128 * ASTRIDE;    // 128 * STRIDEB

    const int tid  = threadIdx.x;
    const int wid  = tid >> 5;
    const int lane = tid & 31;
    const int tq   = lane >> 2;      // 0..7
    const int tr   = lane & 3;       // 0..3
    const int wm   = wid & 3;        // 4 warps along M (32 rows each)
    const int wn   = wid >> 2;       // 2 warps along N (64 cols each)
    const int g    = lane >> 3;      // ldmatrix lane group 0..3
    const int lr   = lane & 7;

    // per-lane ldmatrix base addresses (bytes)
    const uint32_t As_u = smem_u32(As);
    const uint32_t Bs_u = smem_u32(Bs);
    // A: reg j needs matrix j = rows(+8 if g odd) x k(+8 if g>=2)
    const uint32_t aBase = As_u + (uint32_t)(wm * 32 + (g & 1) * 8 + lr) * (ASTRIDE * 2)
                                + (uint32_t)((g >> 1) * 8) * 2;
    // B: reg j needs matrix j = n(+8 if g>=2) x k(+8 if g odd)
    const uint32_t bBase = Bs_u + (uint32_t)(wn * 64 + (g >> 1) * 8 + lr) * (STRIDEB * 2)
                                + (uint32_t)((g & 1) * 8) * 2;

    // copy weight image into smem once (16B vectors)
    {
        const float4* bsrc = (const float4*)Bimg;
        float4* bdst = (float4*)Bs;
        constexpr int NV = 128 * STRIDEB * 2 / 16;
        for (int i = tid; i < NV; i += 256) bdst[i] = bsrc[i];
    }

    for (int tile = blockIdx.x; tile < nTiles; tile += gridDim.x) {
        const int m0 = tile * 128;

        float acc[2][8][4];
#pragma unroll
        for (int a = 0; a < 2; a++)
#pragma unroll
            for (int b = 0; b < 8; b++)
#pragma unroll
                for (int q = 0; q < 4; q++) acc[a][b][q] = 0.0f;

        for (int c = 0; c < CHUNKS; ++c) {
            __syncthreads();   // B copy / previous mma reads of As complete

            // convert A chunk c: 128 rows x 64 fp32 -> hi/lo bf16 pairs
            const float* src = (c < CHUNKS / 2) ? A1 : A2;
            int kb = (c & (CHUNKS / 2 - 1)) * 64;
#pragma unroll
            for (int i = 0; i < 16; i++) {
                int p   = i * 256 + tid;
                int row = p >> 5;
                int k2  = p & 31;
                int grow = min(m0 + row, n - 1);
                float2 v = *(const float2*)(src + (size_t)grow * ASTR32 + kb + 2 * k2);
                __nv_bfloat16 h0 = __float2bfloat16_rn(v.x);
                __nv_bfloat16 h1 = __float2bfloat16_rn(v.y);
                __nv_bfloat16 l0 = __float2bfloat16_rn(v.x - __bfloat162float(h0));
                __nv_bfloat16 l1 = __float2bfloat16_rn(v.y - __bfloat162float(h1));
                uint32_t hp = ((uint32_t)__bfloat16_as_ushort(h1) << 16) | __bfloat16_as_ushort(h0);
                uint32_t lp = ((uint32_t)__bfloat16_as_ushort(l1) << 16) | __bfloat16_as_ushort(l0);
                *(uint32_t*)(As + row * ASTRIDE + 2 * k2)      = hp;
                *(uint32_t*)(As + row * ASTRIDE + 64 + 2 * k2) = lp;
            }
            __syncthreads();

#pragma unroll
            for (int ks = 0; ks < 4; ks++) {
                uint32_t ah[2][4], al[2][4], bh[4][4], bl[4][4];
#pragma unroll
                for (int ma = 0; ma < 2; ma++) {
                    uint32_t a = aBase + (uint32_t)(ma * 16 * ASTRIDE * 2 + ks * 32);
                    ldsm_x4(ah[ma], a);
                    ldsm_x4(al[ma], a + 128);          // lo: +64 bf16
                }
#pragma unroll
                for (int p = 0; p < 4; p++) {
                    uint32_t b = bBase + (uint32_t)(p * 16 * STRIDEB * 2 + c * 128 + ks * 32);
                    ldsm_x4(bh[p], b);
                    ldsm_x4(bl[p], b + KTOT * 2);      // lo: +KTOT bf16
                }
#pragma unroll
                for (int ma = 0; ma < 2; ma++)
#pragma unroll
                    for (int p = 0; p < 4; p++) {
                        mma16816(acc[ma][2 * p],     ah[ma], bh[p][0], bh[p][1]);
                        mma16816(acc[ma][2 * p + 1], ah[ma], bh[p][2], bh[p][3]);
                        mma16816(acc[ma][2 * p],     al[ma], bh[p][0], bh[p][1]);
                        mma16816(acc[ma][2 * p + 1], al[ma], bh[p][2], bh[p][3]);
                        mma16816(acc[ma][2 * p],     ah[ma], bl[p][0], bl[p][1]);
                        mma16816(acc[ma][2 * p + 1], ah[ma], bl[p][2], bl[p][3]);
                    }
            }
        }

        // epilogue: +bias, relu, float2 stores
#pragma unroll
        for (int ma = 0; ma < 2; ma++) {
            int row = m0 + wm * 32 + ma * 16 + tq;
#pragma unroll
            for (int nb = 0; nb < 8; nb++) {
                int col = wn * 64 + nb * 8 + 2 * tr;
                float2 bv = *(const float2*)(bias + col);
                if (row < n) {
                    float2 o;
                    o.x = acc[ma][nb][0] + bv.x;
                    o.y = acc[ma][nb][1] + bv.y;
                    if (RELU) { o.x = fmaxf(o.x, 0.0f); o.y = fmaxf(o.y, 0.0f); }
                    *(float2*)(out + (size_t)row * 128 + col) = o;
                }
                if (row + 8 < n) {
                    float2 o;
                    o.x = acc[ma][nb][2] + bv.x;
                    o.y = acc[ma][nb][3] + bv.y;
                    if (RELU) { o.x = fmaxf(o.x, 0.0f); o.y = fmaxf(o.y, 0.0f); }
                    *(float2*)(out + (size_t)(row + 8) * 128 + col) = o;
                }
            }
        }
    }
}

// ---------------- global mean pool ----------------
__global__ void pool_zero_kernel(float* out, int G) {
    int i = blockIdx.x * blockDim.x + threadIdx.x;
    if (i < G * 128) out[i] = 0.0f;
    if (i < G) g_gcnt[i] = 0.0f;
}

__global__ void pool_acc_kernel(const float* __restrict__ h,
                                const int* __restrict__ batch,
                                float* __restrict__ out, int n, int G) {
    const int NPW = 16;
    int gw   = (blockIdx.x * blockDim.x + threadIdx.x) >> 5;
    int lane = threadIdx.x & 31;
    int beg = gw * NPW;
    if (beg >= n) return;
    int end = min(beg + NPW, n);
    float a0 = 0, a1 = 0, a2 = 0, a3 = 0;
    int cur = min(max(batch[beg], 0), G - 1);
    int cnt = 0;
    for (int i = beg; i < end; i++) {
        int b = min(max(batch[i], 0), G - 1);
        if (b != cur) {
            atomicAdd(&out[cur * 128 + lane +  0], a0);
            atomicAdd(&out[cur * 128 + lane + 32], a1);
            atomicAdd(&out[cur * 128 + lane + 64], a2);
            atomicAdd(&out[cur * 128 + lane + 96], a3);
            if (lane == 0) atomicAdd(&g_gcnt[cur], (float)cnt);
            a0 = a1 = a2 = a3 = 0.0f;
            cnt = 0;
            cur = b;
        }
        const float* row = h + (size_t)i * 128;
        a0 += row[lane];      a1 += row[lane + 32];
        a2 += row[lane + 64]; a3 += row[lane + 96];
        cnt++;
    }
    atomicAdd(&out[cur * 128 + lane +  0], a0);
    atomicAdd(&out[cur * 128 + lane + 32], a1);
    atomicAdd(&out[cur * 128 + lane + 64], a2);
    atomicAdd(&out[cur * 128 + lane + 96], a3);
    if (lane == 0) atomicAdd(&g_gcnt[cur], (float)cnt);
}

__global__ void pool_div_kernel(float* out, int G) {
    int i = blockIdx.x * blockDim.x + threadIdx.x;
    if (i < G * 128) out[i] /= fmaxf(g_gcnt[i >> 7], 1.0f);
}

// ---------------- launch ----------------
extern "C" void kernel_launch(void* const* d_in, const int* in_sizes, int n_in,
                              void* d_out, int out_size) {
    const float* x     = (const float*)d_in[0];
    const int*   ei    = (const int*)d_in[1];
    const int*   batch = (const int*)d_in[2];
    const float* Wl1 = (const float*)d_in[3];
    const float* bl1 = (const float*)d_in[4];
    const float* Wr1 = (const float*)d_in[5];
    const float* Wl2 = (const float*)d_in[6];
    const float* bl2 = (const float*)d_in[7];
    const float* Wr2 = (const float*)d_in[8];
    const float* Wl3 = (const float*)d_in[9];
    const float* bl3 = (const float*)d_in[10];
    const float* Wr3 = (const float*)d_in[11];
    float* out = (float*)d_out;

    const int n = in_sizes[0] / 64;       // 50000
    const int E = in_sizes[1] / 2;        // 600000
    const int G = out_size / 128;         // 64

    const int* src = ei;
    const int* dst = ei + E;

    void *p_agg, *p_hA, *p_hB, *p_Bimg;
    cudaGetSymbolAddress(&p_agg, g_agg);
    cudaGetSymbolAddress(&p_hA, g_hA);
    cudaGetSymbolAddress(&p_hB, g_hB);
    cudaGetSymbolAddress(&p_Bimg, g_Bimg);
    float* agg = (float*)p_agg;
    float* hA  = (float*)p_hA;
    float* hB  = (float*)p_hB;
    unsigned short* Bimg = (unsigned short*)p_Bimg;

    const int smem1 = (128 * 136 + 128 * 264) * 2;   // 102400 (CHUNKS=2)
    const int smem2 = (128 * 136 + 128 * 520) * 2;   // 167936 (CHUNKS=4)
    cudaFuncSetAttribute(sage_mma<2, true >, cudaFuncAttributeMaxDynamicSharedMemorySize, smem1);
    cudaFuncSetAttribute(sage_mma<4, true >, cudaFuncAttributeMaxDynamicSharedMemorySize, smem2);
    cudaFuncSetAttribute(sage_mma<4, false>, cudaFuncAttributeMaxDynamicSharedMemorySize, smem2);

    // ---- weight images (padded [n][2K+8] bf16 hi/lo) ----
    prep_B_kernel<<<(128 * 264 + 255) / 256, 256>>>(Wl1, Wr1, Bimg,          2);
    prep_B_kernel<<<(128 * 520 + 255) / 256, 256>>>(Wl2, Wr2, Bimg + 33792,  4);
    prep_B_kernel<<<(128 * 520 + 255) / 256, 256>>>(Wl3, Wr3, Bimg + 100352, 4);

    // ---- CSR build ----
    zero_deg_kernel<<<(n + 255) / 256, 256>>>(n);
    count_deg_kernel<<<(E + 255) / 256, 256>>>(dst, E, n);
    scan_kernel<<<1, 1024>>>(n);
    scatter_kernel<<<(E + 255) / 256, 256>>>(src, dst, E, n);

    const int aggBlocks = (n * 32 + 255) / 256;
    const int nTiles = (n + 127) / 128;
    const int gemmGrid = 148;

    // ---- layer 1 ----
    agg_kernel<64><<<aggBlocks, 256>>>(x, agg, n);
    sage_mma<2, true><<<gemmGrid, 256, smem1>>>(agg, x, Bimg, bl1, hA, n, nTiles);

    // ---- layer 2 ----
    agg_kernel<128><<<aggBlocks, 256>>>(hA, agg, n);
    sage_mma<4, true><<<gemmGrid, 256, smem2>>>(agg, hA, Bimg + 33792, bl2, hB, n, nTiles);

    // ---- layer 3 ----
    agg_kernel<128><<<aggBlocks, 256>>>(hB, agg, n);
    sage_mma<4, false><<<gemmGrid, 256, smem2>>>(agg, hB, Bimg + 100352, bl3, hA, n, nTiles);

    // ---- global mean pool ----
    pool_zero_kernel<<<(G * 128 + 255) / 256, 256>>>(out, G);
    int poolWarps = (n + 15) / 16;
    pool_acc_kernel<<<(poolWarps * 32 + 255) / 256, 256>>>(hA, batch, out, n, G);
    pool_div_kernel<<<(G * 128 + 255) / 256, 256>>>(out, G);
}